// round 15
// baseline (speedup 1.0000x reference)
#include <cuda_runtime.h>
#include <cuda_bf16.h>
#include <cstdint>
#include <cstddef>

#define NUM_LAYERS 6

// ---------------------------------------------------------------------------
// Algebra (verified): compute on 64x64 conv pixels; per-pixel state:
//   u (=x1+x2), bst (=x2).
//   ph0: bst = WB*x + bb          ph1: u = WU*x + ub
//   ph2..7 (layer l): h = WL[l,b]*u ; bst += gelu(h) ; u += bst
//   out = 0.5*u replicated 2x2.
// Engine: mma.sync.m16n8k16 bf16, 2-term bf16 split both operands, 3 passes
// (hi*hi + lo*hi + hi*lo), f32 accum.
// R13: warp-private fragment-major weight ring (verified win).
// R14: fully unrolled k-loop, compile-time ring slots (verified win).
// R15: scheduling freedom — mma asm non-volatile (pure reg ops), smem loads
// non-volatile with "memory" clobber; cp.async fences keep volatile+memory.
// ptxas can now pipeline step ks+1 loads under step ks's mma tail.
// ---------------------------------------------------------------------------

__device__ float g_alpha[NUM_LAYERS * 4 * 256];
// uint4 idx = (pb*16+ks)*1024 + wid*128 + frag*32 + lane,  frag = hl*2 + mt
__device__ __nv_bfloat16 g_w[4194304];  // 8 MB
__device__ float g_bias_u[256];
__device__ float g_bias_b[256];

__global__ void prep_alpha(const float* __restrict__ affine_w,
                           const float* __restrict__ affine_b,
                           const float* __restrict__ mod_w,
                           const float* __restrict__ y) {
    int o = blockIdx.x, lay = blockIdx.y, t = threadIdx.x;
    const float* awr = affine_w + ((size_t)(lay * 256 + o)) * 512;
    float s0 = 0.f, s1 = 0.f, s2 = 0.f, s3 = 0.f, q = 0.f;
    for (int i = t; i < 512; i += 128) {
        float a = awr[i];
        s0 += a * y[i]; s1 += a * y[512 + i];
        s2 += a * y[1024 + i]; s3 += a * y[1536 + i];
    }
    const float* mwr = mod_w + ((size_t)(lay * 256 + o)) * 256;
    for (int i = t; i < 256; i += 128) { float m = mwr[i]; q += m * m; }
#pragma unroll
    for (int d = 16; d >= 1; d >>= 1) {
        s0 += __shfl_xor_sync(0xffffffffu, s0, d);
        s1 += __shfl_xor_sync(0xffffffffu, s1, d);
        s2 += __shfl_xor_sync(0xffffffffu, s2, d);
        s3 += __shfl_xor_sync(0xffffffffu, s3, d);
        q  += __shfl_xor_sync(0xffffffffu, q, d);
    }
    __shared__ float red[4][5];
    int w = t >> 5;
    if ((t & 31) == 0) { red[w][0]=s0; red[w][1]=s1; red[w][2]=s2; red[w][3]=s3; red[w][4]=q; }
    __syncthreads();
    if (t == 0) {
        float S0=0,S1=0,S2=0,S3=0,Q=0;
#pragma unroll
        for (int i = 0; i < 4; i++) {
            S0+=red[i][0]; S1+=red[i][1]; S2+=red[i][2]; S3+=red[i][3]; Q+=red[i][4];
        }
        float bias = affine_b[lay * 256 + o];
        float S[4] = {S0, S1, S2, S3};
#pragma unroll
        for (int b = 0; b < 4; b++) {
            float sp = S[b] + bias + 1.f;
            g_alpha[(lay * 4 + b) * 256 + o] = sp * rsqrtf(sp * sp * Q + 1e-8f);
        }
    }
}

__global__ void prep_bias(const float* __restrict__ cb) {
    int j = threadIdx.x;
    float c2v = cb[128 + (j >> 1)];
    g_bias_b[j] = c2v;
    g_bias_u[j] = cb[j >> 1] + c2v;
}

// fragment-major weight pack (verified): 16B per (wid, frag, lane)
__global__ void prep_w(const float* __restrict__ cw, const float* __restrict__ mw) {
    int pb = blockIdx.x;   // phase*4+b
    int ks = blockIdx.y;   // 0..15
    int phase = pb >> 2, b = pb & 3;
    size_t base = ((size_t)(pb * 16 + ks)) * 1024;  // uint4 units
#pragma unroll
    for (int it = 0; it < 4; it++) {
        int e = it * 256 + threadIdx.x;   // 0..1023
        int wid = e >> 7, frag = (e >> 5) & 3, lane = e & 31;
        int hl = frag >> 1, mt = frag & 1;
        int o0 = wid * 32 + mt * 16 + (lane >> 2);
        int k0 = ks * 16 + (lane & 3) * 2;
        __nv_bfloat16 v8[8];
#pragma unroll
        for (int j = 0; j < 8; j++) {
            int o = o0 + ((j & 2) ? 8 : 0);
            int k = k0 + (j & 1) + ((j & 4) ? 8 : 0);
            float wv;
            if (phase == 0)      wv = cw[(128 + (o >> 1)) * 256 + k];
            else if (phase == 1) wv = cw[(o >> 1) * 256 + k] + cw[(128 + (o >> 1)) * 256 + k];
            else                 wv = mw[((size_t)((phase - 2) * 256 + o)) * 256 + k] *
                                      g_alpha[((phase - 2) * 4 + b) * 256 + o];
            __nv_bfloat16 hi = __float2bfloat16(wv);
            v8[j] = (hl == 0) ? hi : __float2bfloat16(wv - __bfloat162float(hi));
        }
        *((uint4*)g_w + base + e) = *(const uint4*)v8;
    }
}

__device__ __forceinline__ uint32_t bf2pack(float f0, float f1) {
    __nv_bfloat162 v;
    v.x = __float2bfloat16(f0);
    v.y = __float2bfloat16(f1);
    return *reinterpret_cast<uint32_t*>(&v);
}
__device__ __forceinline__ float2 bf2unpack(uint32_t w) {
    __nv_bfloat162 v = *reinterpret_cast<__nv_bfloat162*>(&w);
    return make_float2(__bfloat162float(v.x), __bfloat162float(v.y));
}
__device__ __forceinline__ float bflo(float f) {
    return f - __bfloat162float(__float2bfloat16(f));
}
__device__ __forceinline__ float gelu_exact(float x) {
    return 0.5f * x * (1.f + erff(x * 0.70710678118654752440f));
}
// non-volatile + memory clobber: ordered vs cp fences & C smem ops, but mmas
// may be interleaved around them by the scheduler.
__device__ __forceinline__ void ldsm4t(uint32_t* d, uint32_t addr) {
    asm("ldmatrix.sync.aligned.m8n8.x4.trans.shared.b16 {%0,%1,%2,%3}, [%4];"
        : "=r"(d[0]), "=r"(d[1]), "=r"(d[2]), "=r"(d[3]) : "r"(addr) : "memory");
}
__device__ __forceinline__ uint4 lds128(uint32_t addr) {
    uint4 v;
    asm("ld.shared.v4.u32 {%0,%1,%2,%3}, [%4];"
        : "=r"(v.x), "=r"(v.y), "=r"(v.z), "=r"(v.w) : "r"(addr) : "memory");
    return v;
}
// pure register op: non-volatile, no memory clobber -> freely schedulable
__device__ __forceinline__ void mma16816(float* c, const uint32_t* a, const uint32_t* b) {
    asm("mma.sync.aligned.m16n8k16.row.col.f32.bf16.bf16.f32 "
        "{%0,%1,%2,%3}, {%4,%5,%6,%7}, {%8,%9}, {%0,%1,%2,%3};"
        : "+f"(c[0]), "+f"(c[1]), "+f"(c[2]), "+f"(c[3])
        : "r"(a[0]), "r"(a[1]), "r"(a[2]), "r"(a[3]), "r"(b[0]), "r"(b[1]));
}
__device__ __forceinline__ void cp16(char* dst_s, const char* src_g) {
    unsigned sd = (unsigned)__cvta_generic_to_shared(dst_s);
    asm volatile("cp.async.cg.shared.global [%0], [%1], 16;\n"
                 :: "r"(sd), "l"(src_g) : "memory");
}
__device__ __forceinline__ void cp16p(char* dst_s, const char* src_g, bool pred) {
    unsigned sd = (unsigned)__cvta_generic_to_shared(dst_s);
    if (pred)
        asm volatile("cp.async.cg.shared.global [%0], [%1], 16;\n"
                     :: "r"(sd), "l"(src_g) : "memory");
}
#define CP_COMMIT() asm volatile("cp.async.commit_group;\n" ::: "memory")
#define CP_WAIT2()  asm volatile("cp.async.wait_group 2;\n" ::: "memory")

// 2 m-tiles x 4 n-tiles of mma into acc, A as register fragments
__device__ __forceinline__ void mma8p(float acc[2][4][4],
                                      const uint4& A0, const uint4& A1,
                                      const uint32_t* B0, const uint32_t* B1) {
    const uint32_t* Am[2] = {(const uint32_t*)&A0, (const uint32_t*)&A1};
#pragma unroll
    for (int mt = 0; mt < 2; mt++) {
#pragma unroll
        for (int j = 0; j < 4; j++) {
            const uint32_t* bp = (j < 2) ? (B0 + (j & 1) * 2) : (B1 + (j & 1) * 2);
            mma16816(acc[mt][j], Am[mt], bp);
        }
    }
}

// SMEM: u planes [256 ch][32 px] bf16 (row stride 80B) + 4-slot ring (64KB)
#define U_HI 0
#define U_LO 20480
#define RING 40960
#define SMEM_BYTES 106496

// grid (128 px-tiles, 4 batches), 256 threads, 2 CTAs/SM.
__global__ __launch_bounds__(256, 2)
void fused_mma(const float* __restrict__ x, float* __restrict__ out) {
    extern __shared__ char sm[];
    uint32_t smb;
    asm("{ .reg .u64 t; cvta.to.shared.u64 t, %1; cvt.u32.u64 %0, t; }"
        : "=r"(smb) : "l"(sm));
    const int t = threadIdx.x, lane = t & 31, wid = t >> 5;
    const int tile = blockIdx.x, b = blockIdx.y;

    // per-thread warp-private ring offset: [wid][frag][lane] 16B units
    const uint32_t wlo = (uint32_t)(wid * 2048 + lane * 16);
    const char* gwb = (const char*)g_w;
    char* ringp = sm + RING;

    // prologue prefetch: phase-0 steps 0..2 (slots 0..2)
    {
        const char* p0 = gwb + (size_t)(b << 18) + wlo;
#pragma unroll
        for (int s = 0; s < 3; s++) {
            const char* sp_ = p0 + (s << 14);
            char* dp_ = ringp + (s << 14) + wlo;
            cp16(dp_,        sp_);
            cp16(dp_ + 512,  sp_ + 512);
            cp16(dp_ + 1024, sp_ + 1024);
            cp16(dp_ + 1536, sp_ + 1536);
            CP_COMMIT();
        }
    }

    // ---- stage input x tile (32 px) into u planes (bf16 split) ----
    {
        const float* xb = x + ((size_t)b << 20) + tile * 32;
#pragma unroll
        for (int it = 0; it < 8; it++) {
            int e4 = it * 256 + t;
            int c = e4 >> 3, p = (e4 & 7) * 4;
            float4 v = *(const float4*)(xb + ((size_t)c << 12) + p);
            uint32_t off = c * 80 + p * 2;
            uint2 hw, lw;
            hw.x = bf2pack(v.x, v.y); hw.y = bf2pack(v.z, v.w);
            lw.x = bf2pack(bflo(v.x), bflo(v.y)); lw.y = bf2pack(bflo(v.z), bflo(v.w));
            *(uint2*)(sm + U_HI + off) = hw;
            *(uint2*)(sm + U_LO + off) = lw;
        }
    }
    __syncthreads();

    // lane/warp constants
    const int g = lane >> 2, tq = lane & 3;
    const int q = lane >> 3, r = lane & 7;
    const int o_base = wid * 32;
    const int chl = r + ((q & 1) << 3);
    uint32_t boff[2];
#pragma unroll
    for (int h = 0; h < 2; h++) {
        int po = h * 16 + ((q >> 1) << 3);
        boff[h] = chl * 80 + po * 2;
    }

    float bst[2][4][4];

#pragma unroll 1
    for (int phase = 0; phase < 8; phase++) {
        // per-phase weight pointers (this thread's slice base)
        const char* curw = gwb + (size_t)(((phase << 2) + b) << 18) + wlo;
        const char* nxtw = (phase < 7)
            ? gwb + (size_t)((((phase + 1) << 2) + b) << 18) + wlo
            : curw;  // dummy, predicated off
        const bool has_next = (phase < 7);

        float acc[2][4][4];
#pragma unroll
        for (int mt = 0; mt < 2; mt++)
#pragma unroll
            for (int j = 0; j < 4; j++)
#pragma unroll
                for (int i = 0; i < 4; i++) acc[mt][j][i] = 0.f;

        // fully unrolled warp-autonomous k-loop: NO barriers, compile-time
        // ring slots & smem offsets; scheduler free to pipeline across steps.
#pragma unroll
        for (int ks = 0; ks < 16; ks++) {
            CP_WAIT2();
            // prefetch step ks+3 (slot (ks+3)&3), crossing into next phase
            {
                const bool in_cur = (ks < 13);
                const bool do_issue = in_cur || has_next;
                const char* sp_ = in_cur ? curw + ((ks + 3) << 14)
                                         : nxtw + ((ks - 13) << 14);
                char* dp_ = ringp + (((ks + 3) & 3) << 14) + wlo;
                cp16p(dp_,        sp_,        do_issue);
                cp16p(dp_ + 512,  sp_ + 512,  do_issue);
                cp16p(dp_ + 1024, sp_ + 1024, do_issue);
                cp16p(dp_ + 1536, sp_ + 1536, do_issue);
                CP_COMMIT();
            }
            uint32_t abase = smb + RING + ((ks & 3) << 14) + wlo;
            uint4 Ahi0 = lds128(abase);
            uint4 Ahi1 = lds128(abase + 512);
            uint4 Alo0 = lds128(abase + 1024);
            uint4 Alo1 = lds128(abase + 1536);
            uint32_t uh = smb + U_HI + ks * 1280;
            uint32_t ul = smb + U_LO + ks * 1280;
            uint32_t B0[4], B1[4], C0[4], C1[4];
            ldsm4t(B0, uh + boff[0]);
            ldsm4t(B1, uh + boff[1]);
            ldsm4t(C0, ul + boff[0]);
            ldsm4t(C1, ul + boff[1]);
            mma8p(acc, Ahi0, Ahi1, B0, B1);    // Whi * uhi
            mma8p(acc, Alo0, Alo1, B0, B1);    // Wlo * uhi (B dies here)
            mma8p(acc, Ahi0, Ahi1, C0, C1);    // Whi * ulo (C consumed last)
        }
        __syncthreads();   // all warps' u reads done before epilogue writes

        // ---- epilogue (thread-owned fragment elements) ----
#pragma unroll
        for (int mt = 0; mt < 2; mt++)
#pragma unroll
        for (int nt = 0; nt < 4; nt++)
#pragma unroll
        for (int i2 = 0; i2 < 2; i2++) {
            float h0 = acc[mt][nt][i2 * 2], h1 = acc[mt][nt][i2 * 2 + 1];
            int o_r = o_base + mt * 16 + g + i2 * 8;
            int px_p = nt * 8 + tq * 2;
            uint32_t off = o_r * 80 + px_p * 2;
            if (phase == 0) {
                float bb = g_bias_b[o_r];
                bst[mt][nt][i2 * 2]     = h0 + bb;
                bst[mt][nt][i2 * 2 + 1] = h1 + bb;
            } else if (phase == 1) {
                float bu = g_bias_u[o_r];
                float u0 = h0 + bu, u1 = h1 + bu;
                *(uint32_t*)(sm + U_HI + off) = bf2pack(u0, u1);
                *(uint32_t*)(sm + U_LO + off) = bf2pack(bflo(u0), bflo(u1));
            } else {
                float2 uhv = bf2unpack(*(uint32_t*)(sm + U_HI + off));
                float2 ulv = bf2unpack(*(uint32_t*)(sm + U_LO + off));
                float u0 = uhv.x + ulv.x, u1 = uhv.y + ulv.y;
                float* bs = &bst[mt][nt][i2 * 2];
                bs[0] += gelu_exact(h0);
                bs[1] += gelu_exact(h1);
                float un0 = u0 + bs[0], un1 = u1 + bs[1];
                if (phase == 7) {
                    int q0 = tile * 32 + px_p;
                    int qh = q0 >> 6, qw = q0 & 63;
                    float v0 = 0.5f * un0, v1 = 0.5f * un1;
                    float4 vv = make_float4(v0, v0, v1, v1);
                    float* pr = out + ((size_t)b << 22) + ((size_t)o_r << 14) +
                                ((size_t)(qh * 2) << 7) + qw * 2;
                    *(float4*)pr = vv;
                    *(float4*)(pr + 128) = vv;
                } else {
                    *(uint32_t*)(sm + U_HI + off) = bf2pack(un0, un1);
                    *(uint32_t*)(sm + U_LO + off) = bf2pack(bflo(un0), bflo(un1));
                }
            }
        }
        __syncthreads();   // u writes visible before next phase's ldsm
    }
}

extern "C" void kernel_launch(void* const* d_in, const int* in_sizes, int n_in,
                              void* d_out, int out_size) {
    const float* x  = (const float*)d_in[0];
    const float* y  = (const float*)d_in[1];
    const float* cw = (const float*)d_in[2];
    const float* cb = (const float*)d_in[3];
    const float* aw = (const float*)d_in[4];
    const float* ab = (const float*)d_in[5];
    const float* mw = (const float*)d_in[6];
    float* out = (float*)d_out;

    prep_alpha<<<dim3(256, NUM_LAYERS), 128>>>(aw, ab, mw, y);
    prep_bias<<<1, 256>>>(cb);
    prep_w<<<dim3(32, 16), 256>>>(cw, mw);

    cudaFuncSetAttribute(fused_mma, cudaFuncAttributeMaxDynamicSharedMemorySize,
                         SMEM_BYTES);
    fused_mma<<<dim3(128, 4), 256, SMEM_BYTES>>>(x, out);
}

// round 16
// speedup vs baseline: 1.0359x; 1.0359x over previous
#include <cuda_runtime.h>
#include <cuda_bf16.h>
#include <cstdint>
#include <cstddef>

#define NUM_LAYERS 6

// ---------------------------------------------------------------------------
// Algebra (verified): compute on 64x64 conv pixels; per-pixel state:
//   u (=x1+x2), bst (=x2).
//   ph0: bst = WB*x + bb          ph1: u = WU*x + ub
//   ph2..7 (layer l): h = WL[l,b]*u ; bst += gelu(h) ; u += bst
//   out = 0.5*u replicated 2x2.
// Engine: mma.sync.m16n8k16 bf16, 2-term bf16 split both operands, 3 passes
// (hi*hi + lo*hi + hi*lo), f32 accum.
// R13/R14 (verified): warp-private fragment-major weights, unrolled k-loop.
// R16: bst state moved regs->SMEM (frees 32 regs); A-operand SMEM ring
// DELETED — weights stream fragment-major via ld.global.nc.v4 into a 2-deep
// register double-buffer (prefetch ks+1 during ks; phase-crossing step-0
// prefetch covered by the epilogue). No cp.async machinery in the k-loop.
// ---------------------------------------------------------------------------

__device__ float g_alpha[NUM_LAYERS * 4 * 256];
// uint4 idx = (pb*16+ks)*1024 + wid*128 + frag*32 + lane,  frag = hl*2 + mt
__device__ __nv_bfloat16 g_w[4194304];  // 8 MB
__device__ float g_bias_u[256];
__device__ float g_bias_b[256];

__global__ void prep_alpha(const float* __restrict__ affine_w,
                           const float* __restrict__ affine_b,
                           const float* __restrict__ mod_w,
                           const float* __restrict__ y) {
    int o = blockIdx.x, lay = blockIdx.y, t = threadIdx.x;
    const float* awr = affine_w + ((size_t)(lay * 256 + o)) * 512;
    float s0 = 0.f, s1 = 0.f, s2 = 0.f, s3 = 0.f, q = 0.f;
    for (int i = t; i < 512; i += 128) {
        float a = awr[i];
        s0 += a * y[i]; s1 += a * y[512 + i];
        s2 += a * y[1024 + i]; s3 += a * y[1536 + i];
    }
    const float* mwr = mod_w + ((size_t)(lay * 256 + o)) * 256;
    for (int i = t; i < 256; i += 128) { float m = mwr[i]; q += m * m; }
#pragma unroll
    for (int d = 16; d >= 1; d >>= 1) {
        s0 += __shfl_xor_sync(0xffffffffu, s0, d);
        s1 += __shfl_xor_sync(0xffffffffu, s1, d);
        s2 += __shfl_xor_sync(0xffffffffu, s2, d);
        s3 += __shfl_xor_sync(0xffffffffu, s3, d);
        q  += __shfl_xor_sync(0xffffffffu, q, d);
    }
    __shared__ float red[4][5];
    int w = t >> 5;
    if ((t & 31) == 0) { red[w][0]=s0; red[w][1]=s1; red[w][2]=s2; red[w][3]=s3; red[w][4]=q; }
    __syncthreads();
    if (t == 0) {
        float S0=0,S1=0,S2=0,S3=0,Q=0;
#pragma unroll
        for (int i = 0; i < 4; i++) {
            S0+=red[i][0]; S1+=red[i][1]; S2+=red[i][2]; S3+=red[i][3]; Q+=red[i][4];
        }
        float bias = affine_b[lay * 256 + o];
        float S[4] = {S0, S1, S2, S3};
#pragma unroll
        for (int b = 0; b < 4; b++) {
            float sp = S[b] + bias + 1.f;
            g_alpha[(lay * 4 + b) * 256 + o] = sp * rsqrtf(sp * sp * Q + 1e-8f);
        }
    }
}

__global__ void prep_bias(const float* __restrict__ cb) {
    int j = threadIdx.x;
    float c2v = cb[128 + (j >> 1)];
    g_bias_b[j] = c2v;
    g_bias_u[j] = cb[j >> 1] + c2v;
}

// fragment-major weight pack (verified): 16B per (wid, frag, lane)
__global__ void prep_w(const float* __restrict__ cw, const float* __restrict__ mw) {
    int pb = blockIdx.x;   // phase*4+b
    int ks = blockIdx.y;   // 0..15
    int phase = pb >> 2, b = pb & 3;
    size_t base = ((size_t)(pb * 16 + ks)) * 1024;  // uint4 units
#pragma unroll
    for (int it = 0; it < 4; it++) {
        int e = it * 256 + threadIdx.x;   // 0..1023
        int wid = e >> 7, frag = (e >> 5) & 3, lane = e & 31;
        int hl = frag >> 1, mt = frag & 1;
        int o0 = wid * 32 + mt * 16 + (lane >> 2);
        int k0 = ks * 16 + (lane & 3) * 2;
        __nv_bfloat16 v8[8];
#pragma unroll
        for (int j = 0; j < 8; j++) {
            int o = o0 + ((j & 2) ? 8 : 0);
            int k = k0 + (j & 1) + ((j & 4) ? 8 : 0);
            float wv;
            if (phase == 0)      wv = cw[(128 + (o >> 1)) * 256 + k];
            else if (phase == 1) wv = cw[(o >> 1) * 256 + k] + cw[(128 + (o >> 1)) * 256 + k];
            else                 wv = mw[((size_t)((phase - 2) * 256 + o)) * 256 + k] *
                                      g_alpha[((phase - 2) * 4 + b) * 256 + o];
            __nv_bfloat16 hi = __float2bfloat16(wv);
            v8[j] = (hl == 0) ? hi : __float2bfloat16(wv - __bfloat162float(hi));
        }
        *((uint4*)g_w + base + e) = *(const uint4*)v8;
    }
}

__device__ __forceinline__ uint32_t bf2pack(float f0, float f1) {
    __nv_bfloat162 v;
    v.x = __float2bfloat16(f0);
    v.y = __float2bfloat16(f1);
    return *reinterpret_cast<uint32_t*>(&v);
}
__device__ __forceinline__ float2 bf2unpack(uint32_t w) {
    __nv_bfloat162 v = *reinterpret_cast<__nv_bfloat162*>(&w);
    return make_float2(__bfloat162float(v.x), __bfloat162float(v.y));
}
__device__ __forceinline__ float bflo(float f) {
    return f - __bfloat162float(__float2bfloat16(f));
}
__device__ __forceinline__ float gelu_exact(float x) {
    return 0.5f * x * (1.f + erff(x * 0.70710678118654752440f));
}
__device__ __forceinline__ void ldsm4t(uint32_t* d, uint32_t addr) {
    asm("ldmatrix.sync.aligned.m8n8.x4.trans.shared.b16 {%0,%1,%2,%3}, [%4];"
        : "=r"(d[0]), "=r"(d[1]), "=r"(d[2]), "=r"(d[3]) : "r"(addr) : "memory");
}
// read-only global 16B load (weights; written by prep kernels pre-launch)
__device__ __forceinline__ uint4 ldg128(const char* p) {
    uint4 v;
    asm("ld.global.nc.v4.u32 {%0,%1,%2,%3}, [%4];"
        : "=r"(v.x), "=r"(v.y), "=r"(v.z), "=r"(v.w) : "l"(p));
    return v;
}
// pure register op: freely schedulable
__device__ __forceinline__ void mma16816(float* c, const uint32_t* a, const uint32_t* b) {
    asm("mma.sync.aligned.m16n8k16.row.col.f32.bf16.bf16.f32 "
        "{%0,%1,%2,%3}, {%4,%5,%6,%7}, {%8,%9}, {%0,%1,%2,%3};"
        : "+f"(c[0]), "+f"(c[1]), "+f"(c[2]), "+f"(c[3])
        : "r"(a[0]), "r"(a[1]), "r"(a[2]), "r"(a[3]), "r"(b[0]), "r"(b[1]));
}
// 2 m-tiles x 4 n-tiles of mma into acc, A as register fragments
__device__ __forceinline__ void mma8p(float acc[2][4][4],
                                      const uint4& A0, const uint4& A1,
                                      const uint32_t* B0, const uint32_t* B1) {
    const uint32_t* Am[2] = {(const uint32_t*)&A0, (const uint32_t*)&A1};
#pragma unroll
    for (int mt = 0; mt < 2; mt++) {
#pragma unroll
        for (int j = 0; j < 4; j++) {
            const uint32_t* bp = (j < 2) ? (B0 + (j & 1) * 2) : (B1 + (j & 1) * 2);
            mma16816(acc[mt][j], Am[mt], bp);
        }
    }
}

// SMEM: u planes [256 ch][32 px] bf16 (row stride 80B) + bst f32 [32][256 thr]
#define U_HI 0
#define U_LO 20480
#define BST  40960
#define SMEM_BYTES 73728

// grid (128 px-tiles, 4 batches), 256 threads, 2 CTAs/SM.
__global__ __launch_bounds__(256, 2)
void fused_mma(const float* __restrict__ x, float* __restrict__ out) {
    extern __shared__ char sm[];
    uint32_t smb;
    asm("{ .reg .u64 t; cvta.to.shared.u64 t, %1; cvt.u32.u64 %0, t; }"
        : "=r"(smb) : "l"(sm));
    const int t = threadIdx.x, lane = t & 31, wid = t >> 5;
    const int tile = blockIdx.x, b = blockIdx.y;

    // per-thread fragment-major weight offset: [wid][frag][lane] 16B units
    const uint32_t wlo = (uint32_t)(wid * 2048 + lane * 16);
    const char* gwb = (const char*)g_w;

    // A register double-buffer; preload phase 0, step 0 into buf 0
    uint4 A[2][4];
    {
        const char* p0 = gwb + (size_t)(b << 18) + wlo;
#pragma unroll
        for (int f = 0; f < 4; f++) A[0][f] = ldg128(p0 + f * 512);
    }

    // ---- stage input x tile (32 px) into u planes (bf16 split) ----
    {
        const float* xb = x + ((size_t)b << 20) + tile * 32;
#pragma unroll
        for (int it = 0; it < 8; it++) {
            int e4 = it * 256 + t;
            int c = e4 >> 3, p = (e4 & 7) * 4;
            float4 v = *(const float4*)(xb + ((size_t)c << 12) + p);
            uint32_t off = c * 80 + p * 2;
            uint2 hw, lw;
            hw.x = bf2pack(v.x, v.y); hw.y = bf2pack(v.z, v.w);
            lw.x = bf2pack(bflo(v.x), bflo(v.y)); lw.y = bf2pack(bflo(v.z), bflo(v.w));
            *(uint2*)(sm + U_HI + off) = hw;
            *(uint2*)(sm + U_LO + off) = lw;
        }
    }
    __syncthreads();

    // lane/warp constants
    const int g = lane >> 2, tq = lane & 3;
    const int q = lane >> 3, r = lane & 7;
    const int o_base = wid * 32;
    const int chl = r + ((q & 1) << 3);
    uint32_t boff[2];
#pragma unroll
    for (int h = 0; h < 2; h++) {
        int po = h * 16 + ((q >> 1) << 3);
        boff[h] = chl * 80 + po * 2;
    }

#pragma unroll 1
    for (int phase = 0; phase < 8; phase++) {
        const char* curw = gwb + (size_t)(((phase << 2) + b) << 18) + wlo;
        const char* nxtw = (phase < 7)
            ? gwb + (size_t)((((phase + 1) << 2) + b) << 18) + wlo
            : curw;  // phase 7: harmless dummy prefetch

        float acc[2][4][4];
#pragma unroll
        for (int mt = 0; mt < 2; mt++)
#pragma unroll
            for (int j = 0; j < 4; j++)
#pragma unroll
                for (int i = 0; i < 4; i++) acc[mt][j][i] = 0.f;

        // fully unrolled warp-autonomous k-loop: A streamed via LDG double
        // buffer (prefetch ks+1 during ks; ks=15 prefetches next phase step 0,
        // whose latency is covered by the epilogue below).
#pragma unroll
        for (int ks = 0; ks < 16; ks++) {
            const int cb = ks & 1, nb = cb ^ 1;
            const char* pf = (ks < 15) ? curw + ((ks + 1) << 14) : nxtw;
#pragma unroll
            for (int f = 0; f < 4; f++) A[nb][f] = ldg128(pf + f * 512);

            uint32_t uh = smb + U_HI + ks * 1280;
            uint32_t ul = smb + U_LO + ks * 1280;
            uint32_t B0[4], B1[4], C0[4], C1[4];
            ldsm4t(B0, uh + boff[0]);
            ldsm4t(B1, uh + boff[1]);
            ldsm4t(C0, ul + boff[0]);
            ldsm4t(C1, ul + boff[1]);
            mma8p(acc, A[cb][0], A[cb][1], B0, B1);   // Whi * uhi
            mma8p(acc, A[cb][2], A[cb][3], B0, B1);   // Wlo * uhi (B dies)
            mma8p(acc, A[cb][0], A[cb][1], C0, C1);   // Whi * ulo
        }
        __syncthreads();   // all warps' u reads done before epilogue writes

        // ---- epilogue (thread-owned fragment elements; bst in SMEM) ----
#pragma unroll
        for (int mt = 0; mt < 2; mt++)
#pragma unroll
        for (int nt = 0; nt < 4; nt++)
#pragma unroll
        for (int i2 = 0; i2 < 2; i2++) {
            float h0 = acc[mt][nt][i2 * 2], h1 = acc[mt][nt][i2 * 2 + 1];
            int o_r = o_base + mt * 16 + g + i2 * 8;
            int px_p = nt * 8 + tq * 2;
            uint32_t off = o_r * 80 + px_p * 2;
            const int be = ((mt * 4 + nt) * 2 + i2) * 2;   // bst elem pair
            float* bp0 = (float*)(sm + BST + be * 1024) + t;
            float* bp1 = (float*)(sm + BST + (be + 1) * 1024) + t;
            if (phase == 0) {
                float bb = g_bias_b[o_r];
                bp0[0] = h0 + bb;
                bp1[0] = h1 + bb;
            } else if (phase == 1) {
                float bu = g_bias_u[o_r];
                float u0 = h0 + bu, u1 = h1 + bu;
                *(uint32_t*)(sm + U_HI + off) = bf2pack(u0, u1);
                *(uint32_t*)(sm + U_LO + off) = bf2pack(bflo(u0), bflo(u1));
            } else {
                float2 uhv = bf2unpack(*(uint32_t*)(sm + U_HI + off));
                float2 ulv = bf2unpack(*(uint32_t*)(sm + U_LO + off));
                float u0 = uhv.x + ulv.x, u1 = uhv.y + ulv.y;
                float b0 = bp0[0] + gelu_exact(h0);
                float b1 = bp1[0] + gelu_exact(h1);
                float un0 = u0 + b0, un1 = u1 + b1;
                if (phase == 7) {
                    int q0 = tile * 32 + px_p;
                    int qh = q0 >> 6, qw = q0 & 63;
                    float v0 = 0.5f * un0, v1 = 0.5f * un1;
                    float4 vv = make_float4(v0, v0, v1, v1);
                    float* pr = out + ((size_t)b << 22) + ((size_t)o_r << 14) +
                                ((size_t)(qh * 2) << 7) + qw * 2;
                    *(float4*)pr = vv;
                    *(float4*)(pr + 128) = vv;
                } else {
                    bp0[0] = b0;
                    bp1[0] = b1;
                    *(uint32_t*)(sm + U_HI + off) = bf2pack(un0, un1);
                    *(uint32_t*)(sm + U_LO + off) = bf2pack(bflo(un0), bflo(un1));
                }
            }
        }
        __syncthreads();   // u writes visible before next phase's ldsm
    }
}

extern "C" void kernel_launch(void* const* d_in, const int* in_sizes, int n_in,
                              void* d_out, int out_size) {
    const float* x  = (const float*)d_in[0];
    const float* y  = (const float*)d_in[1];
    const float* cw = (const float*)d_in[2];
    const float* cb = (const float*)d_in[3];
    const float* aw = (const float*)d_in[4];
    const float* ab = (const float*)d_in[5];
    const float* mw = (const float*)d_in[6];
    float* out = (float*)d_out;

    prep_alpha<<<dim3(256, NUM_LAYERS), 128>>>(aw, ab, mw, y);
    prep_bias<<<1, 256>>>(cb);
    prep_w<<<dim3(32, 16), 256>>>(cw, mw);

    cudaFuncSetAttribute(fused_mma, cudaFuncAttributeMaxDynamicSharedMemorySize,
                         SMEM_BYTES);
    fused_mma<<<dim3(128, 4), 256, SMEM_BYTES>>>(x, out);
}